// round 11
// baseline (speedup 1.0000x reference)
#include <cuda_runtime.h>
#include <math.h>

#define BB 8
#define TT 500
#define HH 100
#define LL 80000
#define NBLK 625          // 128-sample CTA tiles in k_main
#define SEQS (BB*HH)
#define CH0 5000          // level-0 chunks of 16  (80000/16)
#define CH1 313           // ceil(5000/16)
#define CH2 20            // ceil(313/16)

// ---- static scratch ----
__device__ float g_f0up[BB*LL];        // upsampled f0 [B][L]
__device__ float g_sums0[SEQS*CH0];    // per-(b,h) 16-chunk sequential sums
__device__ float g_S5[SEQS*CH0];       // inclusive scan of sums0 per seq (XLA association)

__device__ __forceinline__ float xadd(float a, float b) { return __fadd_rn(a, b); }
__device__ __forceinline__ float xmul(float a, float b) { return __fmul_rn(a, b); }
__device__ __forceinline__ float xsub(float a, float b) { return __fsub_rn(a, b); }

// XLA divide->multiply-by-reciprocal rewrite, constants NOT reassociated:
//   e = fl( fl(f0up * h) * fl(1/16000) )
// 6.25e-5 decimal == 1/16000 exactly, so the f32 literal == XLA's reciprocal.
#define RECIP_SR 6.25e-5f
__device__ __forceinline__ float elem(float f, float hf) {
    return __fmul_rn(__fmul_rn(f, hf), RECIP_SR);
}

// all-fp32 accurate sin for 0 <= x <= ~1e6.
// q = rint(x*2/pi) < 2^20 exact in f32; 2-term FMA Cody-Waite leaves |r|<=~0.8
// with abs reduction error < ~2e-9; deg-9/8 Taylor. Total err < 3e-7.
__device__ __forceinline__ float sin_f32(float x) {
    float q = rintf(__fmul_rn(x, 0.63661977236758134308f));
    float r = fmaf(-q, 1.57079637050628662109375f, x);   // hi = fl32(pi/2)
    r = fmaf(-q, -4.37113882867379e-8f, r);              // lo = pi/2 - hi
    int qi = (int)q;
    float t2 = __fmul_rn(r, r);
    float ps = r * fmaf(t2, fmaf(t2, fmaf(t2, fmaf(t2, 2.7557319e-6f, -1.9841270e-4f),
                                          8.3333333e-3f), -1.6666667e-1f), 1.0f);
    float pc = fmaf(t2, fmaf(t2, fmaf(t2, fmaf(t2, 2.4801587e-5f, -1.3888889e-3f),
                                      4.1666668e-2f), -0.5f), 1.0f);
    float res = (qi & 1) ? pc : ps;
    return (qi & 2) ? -res : res;
}

// ---- pass 0: upsample f0 (linspace replicated) ----
__global__ void k_f0up(const float* __restrict__ f0) {
    int i = blockIdx.x * blockDim.x + threadIdx.x;
    if (i >= BB * LL) return;
    int b = i / LL, l = i % LL;
    const float DELTA = 499.0f / 79999.0f;
    float pos = xmul((float)l, DELTA);
    int lo = (int)pos; if (lo > TT - 1) lo = TT - 1;
    int hi = lo + 1;   if (hi > TT - 1) hi = TT - 1;
    float w   = xsub(pos, (float)lo);
    float omw = xsub(1.0f, w);
    g_f0up[i] = xadd(xmul(f0[b * TT + lo], omw), xmul(f0[b * TT + hi], w));
}

// ---- pass 1: level-0 chunk sums (sequential 16, XLA naive reduce_window) ----
__global__ void k_sums0() {
    int i = blockIdx.x * blockDim.x + threadIdx.x;
    if (i >= SEQS * CH0) return;
    int seq = i / CH0, c0 = i % CH0;
    int b = seq / HH;
    float hf = (float)((seq % HH) + 1);
    const float4* f = reinterpret_cast<const float4*>(&g_f0up[b * LL + c0 * 16]);
    float s = 0.0f;
    bool first = true;
    #pragma unroll
    for (int v = 0; v < 4; v++) {
        float4 x = f[v];
        float e0 = elem(x.x, hf);
        float e1 = elem(x.y, hf);
        float e2 = elem(x.z, hf);
        float e3 = elem(x.w, hf);
        if (first) { s = e0; first = false; } else s = xadd(s, e0);
        s = xadd(s, e1); s = xadd(s, e2); s = xadd(s, e3);
    }
    g_sums0[i] = s;
}

// ---- pass 2: hierarchical carries per seq (XLA ReduceWindowRewriter, base=16) ----
__global__ void __launch_bounds__(320) k_carry() {
    int seq = blockIdx.x;
    int t = threadIdx.x;
    __shared__ float s0[CH0];      // sums0 row (20 KB)
    __shared__ float s1[CH1];      // level-1 chunk sums
    __shared__ float S313[CH1];    // inclusive scan of s1
    __shared__ float s2[CH2];      // level-2 chunk sums
    __shared__ float S20[CH2];     // inclusive scan of s2

    const float* G = &g_sums0[seq * CH0];
    for (int i = t; i < CH0; i += 320) s0[i] = G[i];
    __syncthreads();

    if (t < CH1) {                               // s1[c1] = seq sum of 16 (last: 8)
        int base = t * 16;
        int n = (base + 16 <= CH0) ? 16 : (CH0 - base);
        float s = s0[base];
        for (int k = 1; k < n; k++) s = xadd(s, s0[base + k]);
        s1[t] = s;
    }
    __syncthreads();
    if (t < CH2) {                               // s2[c2] = seq sum of 16 s1 (last: 9)
        int base = t * 16;
        int n = (base + 16 <= CH1) ? 16 : (CH1 - base);
        float s = s1[base];
        for (int k = 1; k < n; k++) s = xadd(s, s1[base + k]);
        s2[t] = s;
    }
    __syncthreads();
    if (t == 0) {                                // scan 20 = chunks {16, 4}, carry compose
        float a = s2[0]; S20[0] = a;
        for (int k = 1; k < 16; k++) { a = xadd(a, s2[k]); S20[k] = a; }
        float c = S20[15];
        float acc = s2[16]; S20[16] = xadd(c, acc);
        for (int k = 17; k < CH2; k++) { acc = xadd(acc, s2[k]); S20[k] = xadd(c, acc); }
    }
    __syncthreads();
    if (t < CH1) {                               // S313[c1] = excl2 + inner2(seq over s1)
        int c2 = t >> 4, p = t & 15;
        float s = s1[c2 * 16];
        for (int k = 1; k <= p; k++) s = xadd(s, s1[c2 * 16 + k]);
        S313[t] = (c2 == 0) ? s : xadd(S20[c2 - 1], s);
    }
    __syncthreads();
    float* out = &g_S5[seq * CH0];               // S5000[c0] = excl1 + inner1(seq over s0)
    for (int c0 = t; c0 < CH0; c0 += 320) {
        int c1 = c0 >> 4, p = c0 & 15;
        float s = s0[c1 * 16];
        for (int k = 1; k <= p; k++) s = xadd(s, s0[c1 * 16 + k]);
        out[c0] = (c1 == 0) ? s : xadd(S313[c1 - 1], s);
    }
}

// ---- pass 3: per-(b,128-sample tile) CTA: loop harmonics, compose + sin + amp ----
__global__ void __launch_bounds__(128) k_main(const float* __restrict__ amps,
                                              float* __restrict__ out) {
    int cta = blockIdx.x;
    int b = cta / NBLK, j = cta % NBLK;
    int t = threadIdx.x;
    int l = j * 128 + t;

    __shared__ float sF0[128];
    __shared__ float sX[2][128];
    __shared__ float sAmp[300];

    const float DELTA = 499.0f / 79999.0f;
    float pos = xmul((float)l, DELTA);
    int lo = (int)pos; if (lo > TT - 1) lo = TT - 1;
    int hi = lo + 1;   if (hi > TT - 1) hi = TT - 1;
    float w   = xsub(pos, (float)lo);
    float omw = xsub(1.0f, w);

    sF0[t] = g_f0up[b * LL + l];

    float pos0 = xmul((float)(j * 128), DELTA);
    int loMin = (int)pos0; if (loMin > TT - 1) loMin = TT - 1;
    for (int i = t; i < 300; i += 128) {
        int row = loMin + i / 100; if (row > TT - 1) row = TT - 1;
        sAmp[i] = amps[(b * TT + row) * HH + (i % 100)];
    }
    int ro = (lo - loMin) * 100;
    int rh = (hi - loMin) * 100;
    __syncthreads();

    int c0    = l >> 4;          // global 16-chunk index
    int p     = t & 15;          // position within chunk
    int cbase = t & ~15;         // local chunk base
    const float* S5b = &g_S5[(size_t)(b * HH) * CH0];

    float acc = 0.0f;
    #pragma unroll 1
    for (int h = 1; h <= HH; h++) {
        int buf = h & 1;
        sX[buf][t] = elem(sF0[t], (float)h);
        __syncthreads();
        float s = sX[buf][cbase];                 // inner0: sequential within chunk
        for (int k = 1; k <= p; k++) s = xadd(s, sX[buf][cbase + k]);
        float excl = (c0 == 0) ? 0.0f : __ldg(&S5b[(size_t)(h - 1) * CH0 + c0 - 1]);
        float S0 = xadd(excl, s);
        float phase = xmul(S0, 6.28318530717958647692f);
        float sv = sin_f32(phase);
        float av = xadd(xmul(sAmp[ro + h - 1], omw), xmul(sAmp[rh + h - 1], w));
        acc = xadd(acc, xmul(sv, av));
    }
    out[b * LL + l] = acc;
}

extern "C" void kernel_launch(void* const* d_in, const int* in_sizes, int n_in,
                              void* d_out, int out_size) {
    const float* f0   = (const float*)d_in[0];
    const float* amps = (const float*)d_in[1];
    float* out = (float*)d_out;

    k_f0up<<<(BB * LL + 255) / 256, 256>>>(f0);
    k_sums0<<<(SEQS * CH0 + 255) / 256, 256>>>();
    k_carry<<<SEQS, 320>>>();
    k_main<<<BB * NBLK, 128>>>(amps, out);
}

// round 12
// speedup vs baseline: 1.9778x; 1.9778x over previous
#include <cuda_runtime.h>
#include <math.h>

#define BB 8
#define TT 500
#define HH 100
#define LL 80000
#define SEQS (BB*HH)
#define CH0 5000          // level-0 chunks of 16  (80000/16)
#define CH1 313           // ceil(5000/16)
#define CH2 20            // ceil(313/16)
#define CPB 32            // chunks per CTA in k_main
#define CTAS_PER_B 157    // ceil(5000/32)
#define GRP 4             // harmonic groups (25 h each)

// ---- static scratch ----
__device__ float g_f0up[BB*LL];        // upsampled f0 [B][L]
__device__ float g_sums0[SEQS*CH0];    // per-(b,h) 16-chunk sequential sums
__device__ float g_S5[SEQS*CH0];       // inclusive scan of sums0 per seq (XLA association)

__device__ __forceinline__ float xadd(float a, float b) { return __fadd_rn(a, b); }
__device__ __forceinline__ float xmul(float a, float b) { return __fmul_rn(a, b); }
__device__ __forceinline__ float xsub(float a, float b) { return __fsub_rn(a, b); }

// XLA divide->multiply-by-reciprocal rewrite, constants NOT reassociated:
//   e = fl( fl(f0up * h) * fl(1/16000) )
#define RECIP_SR 6.25e-5f
__device__ __forceinline__ float elem(float f, float hf) {
    return __fmul_rn(__fmul_rn(f, hf), RECIP_SR);
}

// all-fp32 accurate sin for 0 <= x <= ~1e6 (verified: rel_err 2e-7 end-to-end)
__device__ __forceinline__ float sin_f32(float x) {
    float q = rintf(__fmul_rn(x, 0.63661977236758134308f));
    float r = fmaf(-q, 1.57079637050628662109375f, x);   // hi = fl32(pi/2)
    r = fmaf(-q, -4.37113882867379e-8f, r);              // lo = pi/2 - hi
    int qi = (int)q;
    float t2 = __fmul_rn(r, r);
    float ps = r * fmaf(t2, fmaf(t2, fmaf(t2, fmaf(t2, 2.7557319e-6f, -1.9841270e-4f),
                                          8.3333333e-3f), -1.6666667e-1f), 1.0f);
    float pc = fmaf(t2, fmaf(t2, fmaf(t2, fmaf(t2, 2.4801587e-5f, -1.3888889e-3f),
                                      4.1666668e-2f), -0.5f), 1.0f);
    float res = (qi & 1) ? pc : ps;
    return (qi & 2) ? -res : res;
}

// ---- pass 0: upsample f0 (linspace replicated) ----
__global__ void k_f0up(const float* __restrict__ f0) {
    int i = blockIdx.x * blockDim.x + threadIdx.x;
    if (i >= BB * LL) return;
    int b = i / LL, l = i % LL;
    const float DELTA = 499.0f / 79999.0f;
    float pos = xmul((float)l, DELTA);
    int lo = (int)pos; if (lo > TT - 1) lo = TT - 1;
    int hi = lo + 1;   if (hi > TT - 1) hi = TT - 1;
    float w   = xsub(pos, (float)lo);
    float omw = xsub(1.0f, w);
    g_f0up[i] = xadd(xmul(f0[b * TT + lo], omw), xmul(f0[b * TT + hi], w));
}

// ---- pass 1: level-0 chunk sums (sequential 16, XLA naive reduce_window) ----
__global__ void k_sums0() {
    int i = blockIdx.x * blockDim.x + threadIdx.x;
    if (i >= SEQS * CH0) return;
    int seq = i / CH0, c0 = i % CH0;
    int b = seq / HH;
    float hf = (float)((seq % HH) + 1);
    const float4* f = reinterpret_cast<const float4*>(&g_f0up[b * LL + c0 * 16]);
    float s = 0.0f;
    bool first = true;
    #pragma unroll
    for (int v = 0; v < 4; v++) {
        float4 x = f[v];
        float e0 = elem(x.x, hf);
        float e1 = elem(x.y, hf);
        float e2 = elem(x.z, hf);
        float e3 = elem(x.w, hf);
        if (first) { s = e0; first = false; } else s = xadd(s, e0);
        s = xadd(s, e1); s = xadd(s, e2); s = xadd(s, e3);
    }
    g_sums0[i] = s;
}

// ---- pass 2: hierarchical carries per seq (XLA ReduceWindowRewriter, base=16) ----
__global__ void __launch_bounds__(320) k_carry() {
    int seq = blockIdx.x;
    int t = threadIdx.x;
    __shared__ float s0[CH0];
    __shared__ float s1[CH1];
    __shared__ float S313[CH1];
    __shared__ float s2[CH2];
    __shared__ float S20[CH2];

    const float* G = &g_sums0[seq * CH0];
    for (int i = t; i < CH0; i += 320) s0[i] = G[i];
    __syncthreads();

    if (t < CH1) {
        int base = t * 16;
        int n = (base + 16 <= CH0) ? 16 : (CH0 - base);
        float s = s0[base];
        for (int k = 1; k < n; k++) s = xadd(s, s0[base + k]);
        s1[t] = s;
    }
    __syncthreads();
    if (t < CH2) {
        int base = t * 16;
        int n = (base + 16 <= CH1) ? 16 : (CH1 - base);
        float s = s1[base];
        for (int k = 1; k < n; k++) s = xadd(s, s1[base + k]);
        s2[t] = s;
    }
    __syncthreads();
    if (t == 0) {
        float a = s2[0]; S20[0] = a;
        for (int k = 1; k < 16; k++) { a = xadd(a, s2[k]); S20[k] = a; }
        float c = S20[15];
        float acc = s2[16]; S20[16] = xadd(c, acc);
        for (int k = 17; k < CH2; k++) { acc = xadd(acc, s2[k]); S20[k] = xadd(c, acc); }
    }
    __syncthreads();
    if (t < CH1) {
        int c2 = t >> 4, p = t & 15;
        float s = s1[c2 * 16];
        for (int k = 1; k <= p; k++) s = xadd(s, s1[c2 * 16 + k]);
        S313[t] = (c2 == 0) ? s : xadd(S20[c2 - 1], s);
    }
    __syncthreads();
    float* out = &g_S5[seq * CH0];
    for (int c0 = t; c0 < CH0; c0 += 320) {
        int c1 = c0 >> 4, p = c0 & 15;
        float s = s0[c1 * 16];
        for (int k = 1; k <= p; k++) s = xadd(s, s0[c1 * 16 + k]);
        out[c0] = (c1 == 0) ? s : xadd(S313[c1 - 1], s);
    }
}

// ---- pass 3: chunk-per-thread, 4 harmonic groups, register accumulators ----
__global__ void __launch_bounds__(128) k_main(const float* __restrict__ amps,
                                              float* __restrict__ out) {
    int cta = blockIdx.x;
    int b = cta / CTAS_PER_B;
    int cbase = (cta % CTAS_PER_B) * CPB;
    int tid = threadIdx.x;
    int cl = tid & (CPB - 1);
    int g  = tid >> 5;
    int c0 = cbase + cl;
    bool active = (c0 < CH0);

    __shared__ float sred[GRP][CPB * 17];   // padded: stride 17 -> conflict-free

    float acc[16];
    #pragma unroll
    for (int k = 0; k < 16; k++) acc[k] = 0.0f;

    if (active) {
        int l0 = c0 * 16;
        const float DELTA = 499.0f / 79999.0f;
        float wreg[16];
        unsigned m = 0;
        int v = 0;
        #pragma unroll
        for (int k = 0; k < 16; k++) {
            float pos = xmul((float)(l0 + k), DELTA);
            int lo = (int)pos; if (lo > TT - 1) lo = TT - 1;
            if (k == 0) v = lo;
            if (lo != v) m |= (1u << k);
            wreg[k] = xsub(pos, (float)lo);
        }
        int r1 = (v + 1 < TT) ? v + 1 : TT - 1;
        int r2 = (v + 2 < TT) ? v + 2 : TT - 1;
        const float* a0p = amps + (size_t)(b * TT + v ) * HH - 1;  // +h -> amp[v][h-1]
        const float* a1p = amps + (size_t)(b * TT + r1) * HH - 1;
        const float* a2p = amps + (size_t)(b * TT + r2) * HH - 1;
        const float4* fp = reinterpret_cast<const float4*>(&g_f0up[b * LL + l0]);
        const float* S5p = g_S5 + (size_t)(b * HH) * CH0 + (c0 - 1);
        int h1 = g * (HH / GRP) + 1;

        #pragma unroll 1
        for (int h = h1; h < h1 + HH / GRP; ++h) {
            float hf = (float)h;
            float A0 = __ldg(a0p + h);
            float A1 = __ldg(a1p + h);
            float A2 = __ldg(a2p + h);
            float excl = (c0 == 0) ? 0.0f : __ldg(S5p + (size_t)(h - 1) * CH0);
            float s = 0.0f;
            #pragma unroll
            for (int q = 0; q < 4; q++) {
                float4 f = __ldg(fp + q);
                float fe[4] = {f.x, f.y, f.z, f.w};
                #pragma unroll
                for (int j = 0; j < 4; j++) {
                    int k = q * 4 + j;
                    float e = elem(fe[j], hf);
                    s = (k == 0) ? e : xadd(s, e);       // exact sequential chain
                    float S0 = xadd(excl, s);
                    float ph = xmul(S0, 6.28318530717958647692f);
                    float sv = sin_f32(ph);
                    float wk  = wreg[k];
                    float omw = xsub(1.0f, wk);
                    bool up = (m >> k) & 1u;
                    float alo = up ? A1 : A0;
                    float ahi = up ? A2 : A1;
                    float av = xadd(xmul(alo, omw), xmul(ahi, wk));
                    acc[k] = xadd(acc[k], xmul(sv, av));
                }
            }
        }
    }

    #pragma unroll
    for (int k = 0; k < 16; k++) sred[g][cl * 17 + k] = acc[k];
    __syncthreads();

    // deterministic fixed-order group reduce; thread handles 4 consecutive samples
    int sidx = tid * 4;                 // 0..508, within one chunk (4|16)
    int clr = sidx >> 4, kr = sidx & 15;
    if (cbase + clr < CH0) {
        float4 o;
        float* po = &o.x;
        #pragma unroll
        for (int j = 0; j < 4; j++) {
            int idx = clr * 17 + kr + j;
            float t0 = xadd(sred[0][idx], sred[1][idx]);
            t0 = xadd(t0, sred[2][idx]);
            t0 = xadd(t0, sred[3][idx]);
            po[j] = t0;
        }
        *reinterpret_cast<float4*>(&out[(size_t)b * LL + cbase * 16 + sidx]) = o;
    }
}

extern "C" void kernel_launch(void* const* d_in, const int* in_sizes, int n_in,
                              void* d_out, int out_size) {
    const float* f0   = (const float*)d_in[0];
    const float* amps = (const float*)d_in[1];
    float* out = (float*)d_out;

    k_f0up<<<(BB * LL + 255) / 256, 256>>>(f0);
    k_sums0<<<(SEQS * CH0 + 255) / 256, 256>>>();
    k_carry<<<SEQS, 320>>>();
    k_main<<<BB * CTAS_PER_B, 128>>>(amps, out);
}

// round 14
// speedup vs baseline: 2.4228x; 1.2249x over previous
#include <cuda_runtime.h>
#include <math.h>

#define BB 8
#define TT 500
#define HH 100
#define LL 80000
#define SEQS (BB*HH)
#define CH0 5000          // level-0 chunks of 16  (80000/16)
#define CH1 313           // ceil(5000/16)
#define CH2 20            // ceil(313/16)
#define CPB 32            // chunks per CTA in k_main
#define CTAS_PER_B 157    // ceil(5000/32)
#define GRP 4             // harmonic groups (25 h each)

// ---- static scratch ----
__device__ float g_f0up[BB*LL];        // upsampled f0 [B][L]
__device__ float g_sums0[SEQS*CH0];    // per-(b,h) 16-chunk sequential sums
__device__ float g_S5[SEQS*CH0];       // inclusive scan of sums0 per seq (XLA association)

__device__ __forceinline__ float xadd(float a, float b) { return __fadd_rn(a, b); }
__device__ __forceinline__ float xmul(float a, float b) { return __fmul_rn(a, b); }
__device__ __forceinline__ float xsub(float a, float b) { return __fsub_rn(a, b); }

// XLA divide->multiply-by-reciprocal rewrite, constants NOT reassociated:
//   e = fl( fl(f0up * h) * fl(1/16000) )
#define RECIP_SR 6.25e-5f
__device__ __forceinline__ float elem(float f, float hf) {
    return __fmul_rn(__fmul_rn(f, hf), RECIP_SR);
}

// fp32 sin, Cody-Waite 2-term pi/2 reduction (exact for q<2^22), deg-7/6 Taylor.
// Max abs err ~3.6e-6 (cos term) — 250x below the 1e-3 gate; sin poly is NOT
// reference-visible rounding, only the phase argument is.
__device__ __forceinline__ float sin_f32(float x) {
    float q = rintf(__fmul_rn(x, 0.63661977236758134308f));
    float r = fmaf(-q, 1.57079637050628662109375f, x);   // hi = fl32(pi/2)
    r = fmaf(-q, -4.37113882867379e-8f, r);              // lo = pi/2 - hi
    int qi = (int)q;
    float t2 = __fmul_rn(r, r);
    float ps = r * fmaf(t2, fmaf(t2, fmaf(t2, -1.9841270e-4f,
                                          8.3333333e-3f), -1.6666667e-1f), 1.0f);
    float pc = fmaf(t2, fmaf(t2, fmaf(t2, -1.3888889e-3f,
                                      4.1666668e-2f), -0.5f), 1.0f);
    float res = (qi & 1) ? pc : ps;
    return (qi & 2) ? -res : res;
}

// ---- pass 0: upsample f0 (linspace replicated) ----
__global__ void k_f0up(const float* __restrict__ f0) {
    int i = blockIdx.x * blockDim.x + threadIdx.x;
    if (i >= BB * LL) return;
    int b = i / LL, l = i % LL;
    const float DELTA = 499.0f / 79999.0f;
    float pos = xmul((float)l, DELTA);
    int lo = (int)pos; if (lo > TT - 1) lo = TT - 1;
    int hi = lo + 1;   if (hi > TT - 1) hi = TT - 1;
    float w   = xsub(pos, (float)lo);
    float omw = xsub(1.0f, w);
    g_f0up[i] = xadd(xmul(f0[b * TT + lo], omw), xmul(f0[b * TT + hi], w));
}

// ---- pass 1: chunk sums; thread-per-(b,c0,hquarter), f0 chunk in registers ----
__global__ void __launch_bounds__(256) k_sums0() {
    int c0 = blockIdx.x * 256 + threadIdx.x;
    if (c0 >= CH0) return;
    int hg = blockIdx.y;            // 0..3 -> harmonics hg*25+1 .. hg*25+25
    int b  = blockIdx.z;
    const float4* fp = reinterpret_cast<const float4*>(&g_f0up[b * LL + c0 * 16]);
    float4 v0 = __ldg(fp), v1 = __ldg(fp + 1), v2 = __ldg(fp + 2), v3 = __ldg(fp + 3);
    float fe[16] = {v0.x, v0.y, v0.z, v0.w, v1.x, v1.y, v1.z, v1.w,
                    v2.x, v2.y, v2.z, v2.w, v3.x, v3.y, v3.z, v3.w};
    float* outp = &g_sums0[(size_t)(b * HH + hg * 25) * CH0 + c0];
    int h1 = hg * 25 + 1;
    #pragma unroll 1
    for (int h = h1; h < h1 + 25; ++h) {
        float hf = (float)h;
        float s = elem(fe[0], hf);                // exact sequential chain of 16
        #pragma unroll
        for (int k = 1; k < 16; k++) s = xadd(s, elem(fe[k], hf));
        *outp = s;
        outp += CH0;
    }
}

// ---- pass 2: hierarchical carries per seq (XLA ReduceWindowRewriter, base=16) ----
__global__ void __launch_bounds__(320) k_carry() {
    int seq = blockIdx.x;
    int t = threadIdx.x;
    __shared__ float s0[CH0];
    __shared__ float s1[CH1];
    __shared__ float S313[CH1];
    __shared__ float s2[CH2];
    __shared__ float S20[CH2];

    const float* G = &g_sums0[seq * CH0];
    for (int i = t; i < CH0; i += 320) s0[i] = G[i];
    __syncthreads();

    if (t < CH1) {
        int base = t * 16;
        int n = (base + 16 <= CH0) ? 16 : (CH0 - base);
        float s = s0[base];
        for (int k = 1; k < n; k++) s = xadd(s, s0[base + k]);
        s1[t] = s;
    }
    __syncthreads();
    if (t < CH2) {
        int base = t * 16;
        int n = (base + 16 <= CH1) ? 16 : (CH1 - base);
        float s = s1[base];
        for (int k = 1; k < n; k++) s = xadd(s, s1[base + k]);
        s2[t] = s;
    }
    __syncthreads();
    if (t == 0) {
        float a = s2[0]; S20[0] = a;
        for (int k = 1; k < 16; k++) { a = xadd(a, s2[k]); S20[k] = a; }
        float c = S20[15];
        float acc = s2[16]; S20[16] = xadd(c, acc);
        for (int k = 17; k < CH2; k++) { acc = xadd(acc, s2[k]); S20[k] = xadd(c, acc); }
    }
    __syncthreads();
    if (t < CH1) {
        int c2 = t >> 4, p = t & 15;
        float s = s1[c2 * 16];
        for (int k = 1; k <= p; k++) s = xadd(s, s1[c2 * 16 + k]);
        S313[t] = (c2 == 0) ? s : xadd(S20[c2 - 1], s);
    }
    __syncthreads();
    float* out = &g_S5[seq * CH0];
    for (int c0 = t; c0 < CH0; c0 += 320) {
        int c1 = c0 >> 4, p = c0 & 15;
        float s = s0[c1 * 16];
        for (int k = 1; k <= p; k++) s = xadd(s, s0[c1 * 16 + k]);
        out[c0] = (c1 == 0) ? s : xadd(S313[c1 - 1], s);
    }
}

// ---- pass 3: chunk-per-thread, 4 harmonic groups, register accumulators ----
__global__ void __launch_bounds__(128) k_main(const float* __restrict__ amps,
                                              float* __restrict__ out) {
    int cta = blockIdx.x;
    int b = cta / CTAS_PER_B;
    int cbase = (cta % CTAS_PER_B) * CPB;
    int tid = threadIdx.x;
    int cl = tid & (CPB - 1);
    int g  = tid >> 5;
    int c0 = cbase + cl;
    bool active = (c0 < CH0);

    __shared__ float sred[GRP][CPB * 17];   // padded: stride 17 -> conflict-free

    float acc[16];
    #pragma unroll
    for (int k = 0; k < 16; k++) acc[k] = 0.0f;

    if (active) {
        int l0 = c0 * 16;
        const float DELTA = 499.0f / 79999.0f;
        float wreg[16];
        unsigned m = 0;
        int v = 0;
        #pragma unroll
        for (int k = 0; k < 16; k++) {
            float pos = xmul((float)(l0 + k), DELTA);
            int lo = (int)pos; if (lo > TT - 1) lo = TT - 1;
            if (k == 0) v = lo;
            if (lo != v) m |= (1u << k);
            wreg[k] = xsub(pos, (float)lo);
        }
        int r1 = (v + 1 < TT) ? v + 1 : TT - 1;
        int r2 = (v + 2 < TT) ? v + 2 : TT - 1;
        const float* a0p = amps + (size_t)(b * TT + v ) * HH - 1;  // +h -> amp[v][h-1]
        const float* a1p = amps + (size_t)(b * TT + r1) * HH - 1;
        const float* a2p = amps + (size_t)(b * TT + r2) * HH - 1;
        const float4* fp = reinterpret_cast<const float4*>(&g_f0up[b * LL + l0]);
        const float* S5p = g_S5 + (size_t)(b * HH) * CH0 + (c0 - 1);
        int h1 = g * (HH / GRP) + 1;

        #pragma unroll 1
        for (int h = h1; h < h1 + HH / GRP; ++h) {
            float hf = (float)h;
            float A0 = __ldg(a0p + h);
            float A1 = __ldg(a1p + h);
            float A2 = __ldg(a2p + h);
            float excl = (c0 == 0) ? 0.0f : __ldg(S5p + (size_t)(h - 1) * CH0);
            float s = 0.0f;
            #pragma unroll
            for (int q = 0; q < 4; q++) {
                float4 f = __ldg(fp + q);
                float fe[4] = {f.x, f.y, f.z, f.w};
                #pragma unroll
                for (int j = 0; j < 4; j++) {
                    int k = q * 4 + j;
                    float e = elem(fe[j], hf);
                    s = (k == 0) ? e : xadd(s, e);       // exact sequential chain
                    float S0 = xadd(excl, s);
                    float ph = xmul(S0, 6.28318530717958647692f);
                    float sv = sin_f32(ph);
                    float wk  = wreg[k];
                    float omw = xsub(1.0f, wk);
                    bool up = (m >> k) & 1u;
                    float alo = up ? A1 : A0;
                    float ahi = up ? A2 : A1;
                    float av = xadd(xmul(alo, omw), xmul(ahi, wk));
                    acc[k] = xadd(acc[k], xmul(sv, av));
                }
            }
        }
    }

    #pragma unroll
    for (int k = 0; k < 16; k++) sred[g][cl * 17 + k] = acc[k];
    __syncthreads();

    // deterministic fixed-order group reduce; thread handles 4 consecutive samples
    int sidx = tid * 4;
    int clr = sidx >> 4, kr = sidx & 15;
    if (cbase + clr < CH0) {
        float4 o;
        float* po = &o.x;
        #pragma unroll
        for (int j = 0; j < 4; j++) {
            int idx = clr * 17 + kr + j;
            float t0 = xadd(sred[0][idx], sred[1][idx]);
            t0 = xadd(t0, sred[2][idx]);
            t0 = xadd(t0, sred[3][idx]);
            po[j] = t0;
        }
        *reinterpret_cast<float4*>(&out[(size_t)b * LL + cbase * 16 + sidx]) = o;
    }
}

extern "C" void kernel_launch(void* const* d_in, const int* in_sizes, int n_in,
                              void* d_out, int out_size) {
    const float* f0   = (const float*)d_in[0];
    const float* amps = (const float*)d_in[1];
    float* out = (float*)d_out;

    k_f0up<<<(BB * LL + 255) / 256, 256>>>(f0);
    dim3 gs((CH0 + 255) / 256, GRP, BB);
    k_sums0<<<gs, 256>>>();
    k_carry<<<SEQS, 320>>>();
    k_main<<<BB * CTAS_PER_B, 128>>>(amps, out);
}

// round 15
// speedup vs baseline: 2.5579x; 1.0558x over previous
#include <cuda_runtime.h>
#include <math.h>

#define BB 8
#define TT 500
#define HH 100
#define LL 80000
#define SEQS (BB*HH)
#define CH0 5000          // level-0 chunks of 16  (80000/16)
#define CH1 313           // ceil(5000/16)
#define CH2 20            // ceil(313/16)
#define CPB 32            // chunks per CTA in k_main
#define CTAS_PER_B 157    // ceil(5000/32)
#define GRP 4             // harmonic groups (25 h each)

// ---- static scratch ----
__device__ float g_f0up[BB*LL];        // upsampled f0 [B][L]
__device__ float g_sums0[SEQS*CH0];    // per-(b,h) 16-chunk sequential sums
__device__ float g_S5[SEQS*CH0];       // inclusive scan of sums0 per seq (XLA association)

__device__ __forceinline__ float xadd(float a, float b) { return __fadd_rn(a, b); }
__device__ __forceinline__ float xmul(float a, float b) { return __fmul_rn(a, b); }
__device__ __forceinline__ float xsub(float a, float b) { return __fsub_rn(a, b); }

// XLA divide->multiply-by-reciprocal rewrite, constants NOT reassociated:
//   e = fl( fl(f0up * h) * fl(1/16000) )
#define RECIP_SR 6.25e-5f
__device__ __forceinline__ float elem(float f, float hf) {
    return __fmul_rn(__fmul_rn(f, hf), RECIP_SR);
}

#define MAGIC_RND 12582912.0f            // 1.5 * 2^23
#define INV_PIO2  0.63661977236758134f
#define PIO2_HI   1.57079637050628662109375f
#define PIO2_LO_N 4.37113882867379e-8f   // pi/2 - PIO2_HI = -4.37e-8; we ADD q*this

// ---- pass 0: upsample f0 (linspace replicated) ----
__global__ void k_f0up(const float* __restrict__ f0) {
    int i = blockIdx.x * blockDim.x + threadIdx.x;
    if (i >= BB * LL) return;
    int b = i / LL, l = i % LL;
    const float DELTA = 499.0f / 79999.0f;
    float pos = xmul((float)l, DELTA);
    int lo = (int)pos; if (lo > TT - 1) lo = TT - 1;
    int hi = lo + 1;   if (hi > TT - 1) hi = TT - 1;
    float w   = xsub(pos, (float)lo);
    float omw = xsub(1.0f, w);
    g_f0up[i] = xadd(xmul(f0[b * TT + lo], omw), xmul(f0[b * TT + hi], w));
}

// ---- pass 1: chunk sums; thread-per-(b,c0,hquarter), f0 chunk in registers ----
__global__ void __launch_bounds__(256) k_sums0() {
    int c0 = blockIdx.x * 256 + threadIdx.x;
    if (c0 >= CH0) return;
    int hg = blockIdx.y;            // 0..3 -> harmonics hg*25+1 .. hg*25+25
    int b  = blockIdx.z;
    const float4* fp = reinterpret_cast<const float4*>(&g_f0up[b * LL + c0 * 16]);
    float4 v0 = __ldg(fp), v1 = __ldg(fp + 1), v2 = __ldg(fp + 2), v3 = __ldg(fp + 3);
    float fe[16] = {v0.x, v0.y, v0.z, v0.w, v1.x, v1.y, v1.z, v1.w,
                    v2.x, v2.y, v2.z, v2.w, v3.x, v3.y, v3.z, v3.w};
    float* outp = &g_sums0[(size_t)(b * HH + hg * 25) * CH0 + c0];
    int h1 = hg * 25 + 1;
    #pragma unroll 1
    for (int h = h1; h < h1 + 25; ++h) {
        float hf = (float)h;
        float s = elem(fe[0], hf);                // exact sequential chain of 16
        #pragma unroll
        for (int k = 1; k < 16; k++) s = xadd(s, elem(fe[k], hf));
        *outp = s;
        outp += CH0;
    }
}

// ---- pass 2: hierarchical carries per seq (XLA ReduceWindowRewriter, base=16) ----
__global__ void __launch_bounds__(320) k_carry() {
    int seq = blockIdx.x;
    int t = threadIdx.x;
    __shared__ float s0[CH0];
    __shared__ float s1[CH1];
    __shared__ float S313[CH1];
    __shared__ float s2[CH2];
    __shared__ float S20[CH2];

    const float* G = &g_sums0[seq * CH0];
    for (int i = t; i < CH0; i += 320) s0[i] = G[i];
    __syncthreads();

    if (t < CH1) {
        int base = t * 16;
        int n = (base + 16 <= CH0) ? 16 : (CH0 - base);
        float s = s0[base];
        for (int k = 1; k < n; k++) s = xadd(s, s0[base + k]);
        s1[t] = s;
    }
    __syncthreads();
    if (t < CH2) {
        int base = t * 16;
        int n = (base + 16 <= CH1) ? 16 : (CH1 - base);
        float s = s1[base];
        for (int k = 1; k < n; k++) s = xadd(s, s1[base + k]);
        s2[t] = s;
    }
    __syncthreads();
    if (t == 0) {
        float a = s2[0]; S20[0] = a;
        for (int k = 1; k < 16; k++) { a = xadd(a, s2[k]); S20[k] = a; }
        float c = S20[15];
        float acc = s2[16]; S20[16] = xadd(c, acc);
        for (int k = 17; k < CH2; k++) { acc = xadd(acc, s2[k]); S20[k] = xadd(c, acc); }
    }
    __syncthreads();
    if (t < CH1) {
        int c2 = t >> 4, p = t & 15;
        float s = s1[c2 * 16];
        for (int k = 1; k <= p; k++) s = xadd(s, s1[c2 * 16 + k]);
        S313[t] = (c2 == 0) ? s : xadd(S20[c2 - 1], s);
    }
    __syncthreads();
    float* out = &g_S5[seq * CH0];
    for (int c0 = t; c0 < CH0; c0 += 320) {
        int c1 = c0 >> 4, p = c0 & 15;
        float s = s0[c1 * 16];
        for (int k = 1; k <= p; k++) s = xadd(s, s0[c1 * 16 + k]);
        out[c0] = (c1 == 0) ? s : xadd(S313[c1 - 1], s);
    }
}

// ---- pass 3: half-chunk-per-thread, 4 harmonic groups; warp-uniform (g,half) ----
__global__ void __launch_bounds__(256, 4) k_main(const float* __restrict__ amps,
                                                 float* __restrict__ out) {
    int cta = blockIdx.x;
    int b = cta / CTAS_PER_B;
    int cbase = (cta % CTAS_PER_B) * CPB;
    int tid = threadIdx.x;
    int cl   = tid & 31;             // chunk within CTA
    int half = (tid >> 5) & 1;       // warp-uniform
    int g    = tid >> 6;             // harmonic group 0..3, warp-uniform
    int c0 = cbase + cl;
    bool active = (c0 < CH0);

    __shared__ float sred[GRP][CPB * 17];   // pad 17 -> conflict-free

    float acc[8];
    #pragma unroll
    for (int k = 0; k < 8; k++) acc[k] = 0.0f;

    if (active) {
        int l0 = c0 * 16;
        int kb = half * 8;
        const float DELTA = 499.0f / 79999.0f;
        float wreg[8];
        unsigned m = 0;
        int v = 0;
        #pragma unroll
        for (int k = 0; k < 8; k++) {
            float pos = xmul((float)(l0 + kb + k), DELTA);
            int lo = (int)pos; if (lo > TT - 1) lo = TT - 1;
            if (k == 0) v = lo;
            if (lo != v) m |= (1u << k);
            wreg[k] = xsub(pos, (float)lo);
        }
        int r1 = (v + 1 < TT) ? v + 1 : TT - 1;
        int r2 = (v + 2 < TT) ? v + 2 : TT - 1;
        const float* a0p = amps + (size_t)(b * TT + v ) * HH - 1;  // +h -> amp[v][h-1]
        const float* a1p = amps + (size_t)(b * TT + r1) * HH - 1;
        const float* a2p = amps + (size_t)(b * TT + r2) * HH - 1;
        const float4* fp = reinterpret_cast<const float4*>(&g_f0up[b * LL + l0]);
        const float* S5p = g_S5 + (size_t)(b * HH) * CH0 + (c0 - 1);
        int h1 = g * (HH / GRP) + 1;

        #pragma unroll 1
        for (int h = h1; h < h1 + HH / GRP; ++h) {
            float hf = (float)h;
            float A0 = __ldg(a0p + h);
            float A1 = __ldg(a1p + h);
            float A2 = __ldg(a2p + h);
            float d0 = xsub(A1, A0);     // relaxed interp (ulp-level, tolerance-safe)
            float d1 = xsub(A2, A1);
            float excl = (c0 == 0) ? 0.0f : __ldg(S5p + (size_t)(h - 1) * CH0);
            float s = 0.0f;
            if (half) {                  // warp-uniform: rebuild exact first-8 prefix
                float4 fa = __ldg(fp), fb = __ldg(fp + 1);
                s = elem(fa.x, hf);
                s = xadd(s, elem(fa.y, hf));
                s = xadd(s, elem(fa.z, hf));
                s = xadd(s, elem(fa.w, hf));
                s = xadd(s, elem(fb.x, hf));
                s = xadd(s, elem(fb.y, hf));
                s = xadd(s, elem(fb.z, hf));
                s = xadd(s, elem(fb.w, hf));
            }
            #pragma unroll
            for (int q = 0; q < 2; q++) {
                float4 f = __ldg(fp + half * 2 + q);
                float fe[4] = {f.x, f.y, f.z, f.w};
                #pragma unroll
                for (int j = 0; j < 4; j++) {
                    int k = q * 4 + j;
                    float e = elem(fe[j], hf);
                    s = (half == 0 && k == 0) ? e : xadd(s, e);  // exact chain
                    float S0 = xadd(excl, s);
                    float x  = xmul(S0, 6.28318530717958647692f);
                    // sin(x): magic rint + 2-term Cody-Waite + deg-7/6 Taylor
                    float qm = fmaf(x, INV_PIO2, MAGIC_RND);
                    int   qi = __float_as_int(qm);
                    float qf = xsub(qm, MAGIC_RND);
                    float r  = fmaf(qf, -PIO2_HI, x);
                    r = fmaf(qf, PIO2_LO_N, r);
                    float t2 = xmul(r, r);
                    float ps = r * fmaf(t2, fmaf(t2, fmaf(t2, -1.9841270e-4f,
                                        8.3333333e-3f), -1.6666667e-1f), 1.0f);
                    float pc = fmaf(t2, fmaf(t2, fmaf(t2, -1.3888889e-3f,
                                        4.1666668e-2f), -0.5f), 1.0f);
                    float sv = (qi & 1) ? pc : ps;
                    sv = (qi & 2) ? -sv : sv;
                    float wk = wreg[k];
                    bool up = (m >> k) & 1u;
                    float av = fmaf(wk, up ? d1 : d0, up ? A1 : A0);
                    acc[k] = fmaf(sv, av, acc[k]);
                }
            }
        }
    }

    {
        int base = cl * 17 + half * 8;
        #pragma unroll
        for (int k = 0; k < 8; k++) sred[g][base + k] = acc[k];
    }
    __syncthreads();

    // deterministic fixed-order group reduce; 2 samples per thread
    int sidx = tid * 2;                  // 0..510
    int clr = sidx >> 4, kr = sidx & 15;
    if (cbase + clr < CH0) {
        float2 o;
        int idx = clr * 17 + kr;
        float t0 = xadd(sred[0][idx], sred[1][idx]);
        t0 = xadd(t0, sred[2][idx]);
        o.x = xadd(t0, sred[3][idx]);
        idx++;
        float t1 = xadd(sred[0][idx], sred[1][idx]);
        t1 = xadd(t1, sred[2][idx]);
        o.y = xadd(t1, sred[3][idx]);
        *reinterpret_cast<float2*>(&out[(size_t)b * LL + cbase * 16 + sidx]) = o;
    }
}

extern "C" void kernel_launch(void* const* d_in, const int* in_sizes, int n_in,
                              void* d_out, int out_size) {
    const float* f0   = (const float*)d_in[0];
    const float* amps = (const float*)d_in[1];
    float* out = (float*)d_out;

    k_f0up<<<(BB * LL + 255) / 256, 256>>>(f0);
    dim3 gs((CH0 + 255) / 256, GRP, BB);
    k_sums0<<<gs, 256>>>();
    k_carry<<<SEQS, 320>>>();
    k_main<<<BB * CTAS_PER_B, 256>>>(amps, out);
}

// round 17
// speedup vs baseline: 2.7178x; 1.0625x over previous
#include <cuda_runtime.h>
#include <math.h>

#define BB 8
#define TT 500
#define HH 100
#define LL 80000
#define SEQS (BB*HH)
#define CH0 5000          // level-0 chunks of 16  (80000/16)
#define CH1 313           // ceil(5000/16)
#define CH2 20            // ceil(313/16)
#define CPB 32            // chunks per CTA in k_main
#define CTAS_PER_B 157    // ceil(5000/32)
#define GRP 4             // harmonic groups (25 h each)

// ---- static scratch ----
__device__ float g_f0up[BB*LL];        // upsampled f0 [B][L]
__device__ float g_sums0[SEQS*CH0];    // per-(b,h) 16-chunk sequential sums
__device__ float g_S5[SEQS*CH0];       // inclusive scan of sums0 per seq (XLA association)

__device__ __forceinline__ float xadd(float a, float b) { return __fadd_rn(a, b); }
__device__ __forceinline__ float xmul(float a, float b) { return __fmul_rn(a, b); }
__device__ __forceinline__ float xsub(float a, float b) { return __fsub_rn(a, b); }

// XLA divide->multiply-by-reciprocal rewrite, constants NOT reassociated:
//   e = fl( fl(f0up * h) * fl(1/16000) )
#define RECIP_SR 6.25e-5f
__device__ __forceinline__ float elem(float f, float hf) {
    return __fmul_rn(__fmul_rn(f, hf), RECIP_SR);
}

#define MAGIC_RND 12582912.0f            // 1.5 * 2^23 (exact int capture, q < 2^22)
#define INV_PI    0.31830988618379067f
#define PI_HI     3.14159274101257324219f   // fl32(pi)
#define PI_LO     -8.74227765734758606e-8f  // pi - PI_HI
#define TWO_PI    6.28318530717958647692f
#define DELTA_LS  (499.0f / 79999.0f)

// ---- pass 1 (fused): f0 upsample + level-0 chunk sums ----
// thread = (b, c0, h-quarter); computes its 16 f0up values from raw f0
// (bit-identical linspace/interp rounding), hg==0 slice also writes g_f0up.
__global__ void __launch_bounds__(256) k_sums0(const float* __restrict__ f0) {
    int c0 = blockIdx.x * 256 + threadIdx.x;
    if (c0 >= CH0) return;
    int hg = blockIdx.y;            // 0..3 -> harmonics hg*25+1 .. hg*25+25
    int b  = blockIdx.z;
    int l0 = c0 * 16;

    const float* fb = f0 + b * TT;
    float fe[16];
    #pragma unroll
    for (int k = 0; k < 16; k++) {
        float pos = xmul((float)(l0 + k), DELTA_LS);
        int lo = (int)pos; if (lo > TT - 1) lo = TT - 1;
        int hi = lo + 1;   if (hi > TT - 1) hi = TT - 1;
        float w   = xsub(pos, (float)lo);
        float omw = xsub(1.0f, w);
        fe[k] = xadd(xmul(__ldg(fb + lo), omw), xmul(__ldg(fb + hi), w));
    }
    if (hg == 0) {
        float4* gp = reinterpret_cast<float4*>(&g_f0up[b * LL + l0]);
        #pragma unroll
        for (int q = 0; q < 4; q++)
            gp[q] = make_float4(fe[q*4], fe[q*4+1], fe[q*4+2], fe[q*4+3]);
    }

    float* outp = &g_sums0[(size_t)(b * HH + hg * 25) * CH0 + c0];
    int h1 = hg * 25 + 1;
    #pragma unroll 1
    for (int h = h1; h < h1 + 25; ++h) {
        float hf = (float)h;
        float s = elem(fe[0], hf);                // exact sequential chain of 16
        #pragma unroll
        for (int k = 1; k < 16; k++) s = xadd(s, elem(fe[k], hf));
        *outp = s;
        outp += CH0;
    }
}

// ---- pass 2: hierarchical carries per seq (XLA ReduceWindowRewriter, base=16) ----
__global__ void __launch_bounds__(320) k_carry() {
    int seq = blockIdx.x;
    int t = threadIdx.x;
    __shared__ float s0[CH0];
    __shared__ float s1[CH1];
    __shared__ float S313[CH1];
    __shared__ float s2[CH2];
    __shared__ float S20[CH2];

    const float* G = &g_sums0[seq * CH0];
    for (int i = t; i < CH0; i += 320) s0[i] = G[i];
    __syncthreads();

    if (t < CH1) {
        int base = t * 16;
        int n = (base + 16 <= CH0) ? 16 : (CH0 - base);
        float s = s0[base];
        for (int k = 1; k < n; k++) s = xadd(s, s0[base + k]);
        s1[t] = s;
    }
    __syncthreads();
    if (t < CH2) {
        int base = t * 16;
        int n = (base + 16 <= CH1) ? 16 : (CH1 - base);
        float s = s1[base];
        for (int k = 1; k < n; k++) s = xadd(s, s1[base + k]);
        s2[t] = s;
    }
    __syncthreads();
    if (t == 0) {
        float a = s2[0]; S20[0] = a;
        for (int k = 1; k < 16; k++) { a = xadd(a, s2[k]); S20[k] = a; }
        float c = S20[15];
        float acc = s2[16]; S20[16] = xadd(c, acc);
        for (int k = 17; k < CH2; k++) { acc = xadd(acc, s2[k]); S20[k] = xadd(c, acc); }
    }
    __syncthreads();
    if (t < CH1) {
        int c2 = t >> 4, p = t & 15;
        float s = s1[c2 * 16];
        for (int k = 1; k <= p; k++) s = xadd(s, s1[c2 * 16 + k]);
        S313[t] = (c2 == 0) ? s : xadd(S20[c2 - 1], s);
    }
    __syncthreads();
    float* out = &g_S5[seq * CH0];
    for (int c0 = t; c0 < CH0; c0 += 320) {
        int c1 = c0 >> 4, p = c0 & 15;
        float s = s0[c1 * 16];
        for (int k = 1; k <= p; k++) s = xadd(s, s0[c1 * 16 + k]);
        out[c0] = (c1 == 0) ? s : xadd(S313[c1 - 1], s);
    }
}

// ---- pass 3: half-chunk-per-thread, 4 harmonic groups; warp-uniform (g,half) ----
__global__ void __launch_bounds__(256, 4) k_main(const float* __restrict__ amps,
                                                 float* __restrict__ out) {
    int cta = blockIdx.x;
    int b = cta / CTAS_PER_B;
    int cbase = (cta % CTAS_PER_B) * CPB;
    int tid = threadIdx.x;
    int cl   = tid & 31;             // chunk within CTA
    int half = (tid >> 5) & 1;       // warp-uniform
    int g    = tid >> 6;             // harmonic group 0..3, warp-uniform
    int c0 = cbase + cl;
    bool active = (c0 < CH0);

    __shared__ float sred[GRP][CPB * 17];   // pad 17 -> conflict-free

    float acc[8];
    #pragma unroll
    for (int k = 0; k < 8; k++) acc[k] = 0.0f;

    if (active) {
        int l0 = c0 * 16;
        int kb = half * 8;
        float wreg[8];
        unsigned m = 0;
        int v = 0;
        #pragma unroll
        for (int k = 0; k < 8; k++) {
            float pos = xmul((float)(l0 + kb + k), DELTA_LS);
            int lo = (int)pos; if (lo > TT - 1) lo = TT - 1;
            if (k == 0) v = lo;
            if (lo != v) m |= (1u << k);
            wreg[k] = xsub(pos, (float)lo);
        }
        int r1 = (v + 1 < TT) ? v + 1 : TT - 1;
        int r2 = (v + 2 < TT) ? v + 2 : TT - 1;
        const float* a0p = amps + (size_t)(b * TT + v ) * HH - 1;  // +h -> amp[v][h-1]
        const float* a1p = amps + (size_t)(b * TT + r1) * HH - 1;
        const float* a2p = amps + (size_t)(b * TT + r2) * HH - 1;
        const float4* fp = reinterpret_cast<const float4*>(&g_f0up[b * LL + l0]);
        const float* S5p = g_S5 + (size_t)(b * HH) * CH0 + (c0 - 1);
        int h1 = g * (HH / GRP) + 1;

        #pragma unroll 1
        for (int h = h1; h < h1 + HH / GRP; ++h) {
            float hf = (float)h;
            float A0 = __ldg(a0p + h);
            float A1 = __ldg(a1p + h);
            float A2 = __ldg(a2p + h);
            float d0 = xsub(A1, A0);     // relaxed interp (ulp-level, tolerance-safe)
            float d1 = xsub(A2, A1);
            float excl = (c0 == 0) ? 0.0f : __ldg(S5p + (size_t)(h - 1) * CH0);
            float s = 0.0f;
            if (half) {                  // warp-uniform: rebuild exact first-8 prefix
                float4 fa = __ldg(fp), fb = __ldg(fp + 1);
                s = elem(fa.x, hf);
                s = xadd(s, elem(fa.y, hf));
                s = xadd(s, elem(fa.z, hf));
                s = xadd(s, elem(fa.w, hf));
                s = xadd(s, elem(fb.x, hf));
                s = xadd(s, elem(fb.y, hf));
                s = xadd(s, elem(fb.z, hf));
                s = xadd(s, elem(fb.w, hf));
            }
            #pragma unroll
            for (int q = 0; q < 2; q++) {
                float4 f = __ldg(fp + half * 2 + q);
                float fe[4] = {f.x, f.y, f.z, f.w};
                #pragma unroll
                for (int j = 0; j < 4; j++) {
                    int k = q * 4 + j;
                    float e = elem(fe[j], hf);
                    s = (half == 0 && k == 0) ? e : xadd(s, e);  // exact chain
                    float S0 = xadd(excl, s);
                    float x  = xmul(S0, TWO_PI);
                    // sin(x): mod-pi magic rint + 2-term Cody-Waite + one deg-9 poly
                    float qm = fmaf(x, INV_PI, MAGIC_RND);
                    int   qi = __float_as_int(qm);
                    float qf = xsub(qm, MAGIC_RND);
                    float r  = fmaf(qf, -PI_HI, x);
                    r = fmaf(qf, -PI_LO, r);
                    float t2 = xmul(r, r);
                    float p  = fmaf(t2, fmaf(t2, fmaf(t2, fmaf(t2,
                                   2.7557319e-6f, -1.9841270e-4f),
                                   8.3333333e-3f), -1.6666667e-1f), 1.0f);
                    float sv = __int_as_float(__float_as_int(xmul(r, p)) ^ (qi << 31));
                    float wk = wreg[k];
                    bool up = (m >> k) & 1u;
                    float av = fmaf(wk, up ? d1 : d0, up ? A1 : A0);
                    acc[k] = fmaf(sv, av, acc[k]);
                }
            }
        }
    }

    {
        int base = cl * 17 + half * 8;
        #pragma unroll
        for (int k = 0; k < 8; k++) sred[g][base + k] = acc[k];
    }
    __syncthreads();

    // deterministic fixed-order group reduce; 2 samples per thread
    int sidx = tid * 2;                  // 0..510
    int clr = sidx >> 4, kr = sidx & 15;
    if (cbase + clr < CH0) {
        float2 o;
        int idx = clr * 17 + kr;
        float t0 = xadd(sred[0][idx], sred[1][idx]);
        t0 = xadd(t0, sred[2][idx]);
        o.x = xadd(t0, sred[3][idx]);
        idx++;
        float t1 = xadd(sred[0][idx], sred[1][idx]);
        t1 = xadd(t1, sred[2][idx]);
        o.y = xadd(t1, sred[3][idx]);
        *reinterpret_cast<float2*>(&out[(size_t)b * LL + cbase * 16 + sidx]) = o;
    }
}

extern "C" void kernel_launch(void* const* d_in, const int* in_sizes, int n_in,
                              void* d_out, int out_size) {
    const float* f0   = (const float*)d_in[0];
    const float* amps = (const float*)d_in[1];
    float* out = (float*)d_out;

    dim3 gs((CH0 + 255) / 256, GRP, BB);
    k_sums0<<<gs, 256>>>(f0);
    k_carry<<<SEQS, 320>>>();
    k_main<<<BB * CTAS_PER_B, 256>>>(amps, out);
}